// round 4
// baseline (speedup 1.0000x reference)
#include <cuda_runtime.h>

// ReLU_Conv (CROWN-style ReLU relaxation over bound maps)
// Round 4: persistent grid (148*3 CTAs), grid-stride over neuron pairs,
//          software prefetch of next pair's loads across the reduce/store
//          tail, double-buffered smem partials (1 barrier/iter),
//          streaming cache hints.
// Output layout: [lx_out | ux_out | lc_out | uc_out]

__device__ __forceinline__ void acc_pair(const float4 l, const float4 u,
                                         const float4 mn, const float4 mx,
                                         float& sl, float& su)
{
    // (l>0 ? mn : (l<0 ? mx : 0)) * l == (l>0 ? mn : mx) * l  (finite bounds)
    sl  = (l.x > 0.f ? mn.x : mx.x) * l.x;
    su  = (u.x > 0.f ? mx.x : mn.x) * u.x;
    sl += (l.y > 0.f ? mn.y : mx.y) * l.y;
    su += (u.y > 0.f ? mx.y : mn.y) * u.y;
    sl += (l.z > 0.f ? mn.z : mx.z) * l.z;
    su += (u.z > 0.f ? mx.z : mn.z) * u.z;
    sl += (l.w > 0.f ? mn.w : mx.w) * l.w;
    su += (u.w > 0.f ? mx.w : mn.w) * u.w;
}

__global__ __launch_bounds__(256, 3)
void relu_conv_persistent(
    const float* __restrict__ lx, const float* __restrict__ ux,
    const float* __restrict__ lc, const float* __restrict__ uc,
    const float* __restrict__ xmin, const float* __restrict__ xmax,
    float* __restrict__ lx_out, float* __restrict__ ux_out,
    float* __restrict__ lc_out, float* __restrict__ uc_out,
    int nPairs)
{
    const int tid  = threadIdx.x;                     // 0..255
    const int warp = tid >> 5, lane = tid & 31;
    const int stride = gridDim.x;

    // Broadcast bounds: loaded once, reused every iteration.
    const float4 vmn = __ldg(reinterpret_cast<const float4*>(xmin) + tid);
    const float4 vmx = __ldg(reinterpret_cast<const float4*>(xmax) + tid);

    __shared__ float4 sL[2][8], sU[2][8];

    int p = blockIdx.x;
    if (p >= nPairs) return;

    // Load first pair (2 neurons = 2048 floats; 4x LDG.128 per thread).
    size_t base = (size_t)p * 2048;
    float4 clx0 = __ldcs(reinterpret_cast<const float4*>(lx + base) + tid);
    float4 cux0 = __ldcs(reinterpret_cast<const float4*>(ux + base) + tid);
    float4 clx1 = __ldcs(reinterpret_cast<const float4*>(lx + base + 1024) + tid);
    float4 cux1 = __ldcs(reinterpret_cast<const float4*>(ux + base + 1024) + tid);

    int buf = 0;
    while (true) {
        const int pn = p + stride;
        const bool has_next = (pn < nPairs);

        // Prefetch next pair: overlaps the reduce/barrier/store tail below.
        float4 nlx0, nux0, nlx1, nux1;
        size_t nbase = (size_t)pn * 2048;
        if (has_next) {
            nlx0 = __ldcs(reinterpret_cast<const float4*>(lx + nbase) + tid);
            nux0 = __ldcs(reinterpret_cast<const float4*>(ux + nbase) + tid);
            nlx1 = __ldcs(reinterpret_cast<const float4*>(lx + nbase + 1024) + tid);
            nux1 = __ldcs(reinterpret_cast<const float4*>(ux + nbase + 1024) + tid);
        }

        // ---- reduce current pair ----
        float sl0, su0, sl1, su1;
        acc_pair(clx0, cux0, vmn, vmx, sl0, su0);
        acc_pair(clx1, cux1, vmn, vmx, sl1, su1);

        #pragma unroll
        for (int off = 16; off; off >>= 1) {
            sl0 += __shfl_down_sync(0xffffffffu, sl0, off);
            su0 += __shfl_down_sync(0xffffffffu, su0, off);
            sl1 += __shfl_down_sync(0xffffffffu, sl1, off);
            su1 += __shfl_down_sync(0xffffffffu, su1, off);
        }
        if (lane == 0) {
            sL[buf][warp] = make_float4(sl0, sl1, 0.f, 0.f);
            sU[buf][warp] = make_float4(su0, su1, 0.f, 0.f);
        }
        __syncthreads();                               // one barrier per iter

        float l0 = 0.f, u0 = 0.f, l1 = 0.f, u1 = 0.f;
        #pragma unroll
        for (int i = 0; i < 8; i++) {
            const float4 pL = sL[buf][i], pU = sU[buf][i];
            l0 += pL.x; l1 += pL.y;
            u0 += pU.x; u1 += pU.y;
        }
        const int n0 = p * 2, n1 = n0 + 1;
        const float lc0 = lc[n0], uc0 = uc[n0];
        const float lc1 = lc[n1], uc1 = uc[n1];
        l0 += lc0; u0 += uc0;
        l1 += lc1; u1 += uc1;

        const bool alive0 = (l0 >= 0.f);
        const bool cross0 = (l0 < 0.f) && (u0 > 0.f);
        float slope0 = cross0 ? (u0 / (u0 - l0)) : 1.f;
        slope0 = fminf(fmaxf(slope0, 0.f), 1.f);

        const bool alive1 = (l1 >= 0.f);
        const bool cross1 = (l1 < 0.f) && (u1 > 0.f);
        float slope1 = cross1 ? (u1 / (u1 - l1)) : 1.f;
        slope1 = fminf(fmaxf(slope1, 0.f), 1.f);

        if (tid == 0) {
            lc_out[n0] = alive0 ? lc0 : 0.f;
            uc_out[n0] = alive0 ? uc0 : (cross0 ? (slope0 * uc0 - slope0 * l0) : 0.f);
            lc_out[n1] = alive1 ? lc1 : 0.f;
            uc_out[n1] = alive1 ? uc1 : (cross1 ? (slope1 * uc1 - slope1 * l1) : 0.f);
        }

        // ---- masked stores of current pair ----
        float4 o;
        o.x = alive0 ? clx0.x : 0.f;  o.y = alive0 ? clx0.y : 0.f;
        o.z = alive0 ? clx0.z : 0.f;  o.w = alive0 ? clx0.w : 0.f;
        __stcs(reinterpret_cast<float4*>(lx_out + base) + tid, o);

        o.x = alive0 ? cux0.x : (cross0 ? slope0 * cux0.x : 0.f);
        o.y = alive0 ? cux0.y : (cross0 ? slope0 * cux0.y : 0.f);
        o.z = alive0 ? cux0.z : (cross0 ? slope0 * cux0.z : 0.f);
        o.w = alive0 ? cux0.w : (cross0 ? slope0 * cux0.w : 0.f);
        __stcs(reinterpret_cast<float4*>(ux_out + base) + tid, o);

        o.x = alive1 ? clx1.x : 0.f;  o.y = alive1 ? clx1.y : 0.f;
        o.z = alive1 ? clx1.z : 0.f;  o.w = alive1 ? clx1.w : 0.f;
        __stcs(reinterpret_cast<float4*>(lx_out + base + 1024) + tid, o);

        o.x = alive1 ? cux1.x : (cross1 ? slope1 * cux1.x : 0.f);
        o.y = alive1 ? cux1.y : (cross1 ? slope1 * cux1.y : 0.f);
        o.z = alive1 ? cux1.z : (cross1 ? slope1 * cux1.z : 0.f);
        o.w = alive1 ? cux1.w : (cross1 ? slope1 * cux1.w : 0.f);
        __stcs(reinterpret_cast<float4*>(ux_out + base + 1024) + tid, o);

        if (!has_next) break;
        clx0 = nlx0; cux0 = nux0; clx1 = nlx1; cux1 = nux1;
        p = pn; base = nbase; buf ^= 1;
    }
}

extern "C" void kernel_launch(void* const* d_in, const int* in_sizes, int n_in,
                              void* d_out, int out_size)
{
    const float* lx   = (const float*)d_in[0];
    const float* ux   = (const float*)d_in[1];
    const float* lc   = (const float*)d_in[2];
    const float* uc   = (const float*)d_in[3];
    const float* xmin = (const float*)d_in[4];
    const float* xmax = (const float*)d_in[5];

    const int neurons = in_sizes[2];          // C*H*W = 32768
    const size_t nel  = (size_t)neurons * 1024;
    const int nPairs  = neurons / 2;          // 16384

    float* out    = (float*)d_out;
    float* lx_out = out;
    float* ux_out = out + nel;
    float* lc_out = out + 2 * nel;
    float* uc_out = out + 2 * nel + neurons;

    const int grid = 148 * 3;                 // persistent: 3 CTAs/SM
    relu_conv_persistent<<<grid, 256>>>(lx, ux, lc, uc, xmin, xmax,
                                        lx_out, ux_out, lc_out, uc_out,
                                        nPairs);
}

// round 5
// speedup vs baseline: 1.0781x; 1.0781x over previous
#include <cuda_runtime.h>

// ReLU_Conv (CROWN-style ReLU relaxation over bound maps)
// Round 5: ONE WARP PER NEURON — no inter-warp barrier in the hot path.
//   Each lane: 8 float4 of lx + 8 float4 of ux (16 front-batched LDG.128),
//   bounds staged in smem (conflict-free stride-32 LDS.128),
//   warp-shuffle reduce, lane-0 finalize, shuffle-broadcast, masked stores.
// Output layout: [lx_out | ux_out | lc_out | uc_out]

__global__ __launch_bounds__(256, 2)
void relu_conv_warp_kernel(
    const float* __restrict__ lx, const float* __restrict__ ux,
    const float* __restrict__ lc, const float* __restrict__ uc,
    const float* __restrict__ xmin, const float* __restrict__ xmax,
    float* __restrict__ lx_out, float* __restrict__ ux_out,
    float* __restrict__ lc_out, float* __restrict__ uc_out)
{
    __shared__ float4 smn[256], smx[256];

    const int tid  = threadIdx.x;
    const int warp = tid >> 5, lane = tid & 31;

    // Stage bounds (8 KB) into smem once; the only barrier in the kernel.
    smn[tid] = __ldg(reinterpret_cast<const float4*>(xmin) + tid);
    smx[tid] = __ldg(reinterpret_cast<const float4*>(xmax) + tid);
    __syncthreads();

    const int n = blockIdx.x * 8 + warp;              // this warp's neuron
    const size_t base = (size_t)n * 1024;

    // Front-batched streaming loads: lane covers float4 slots lane + 32*i.
    const float4* plx = reinterpret_cast<const float4*>(lx + base) + lane;
    const float4* pux = reinterpret_cast<const float4*>(ux + base) + lane;
    float4 vlx[8], vux[8];
    #pragma unroll
    for (int i = 0; i < 8; i++) vlx[i] = __ldcs(plx + i * 32);
    #pragma unroll
    for (int i = 0; i < 8; i++) vux[i] = __ldcs(pux + i * 32);

    // Accumulate against smem-resident bounds.
    float sl = 0.f, su = 0.f;
    #pragma unroll
    for (int i = 0; i < 8; i++) {
        const float4 mn = smn[lane + i * 32];
        const float4 mx = smx[lane + i * 32];
        const float4 l = vlx[i], u = vux[i];
        // (l>0 ? mn : (l<0 ? mx : 0)) * l == (l>0 ? mn : mx) * l (finite bounds)
        sl += (l.x > 0.f ? mn.x : mx.x) * l.x;
        su += (u.x > 0.f ? mx.x : mn.x) * u.x;
        sl += (l.y > 0.f ? mn.y : mx.y) * l.y;
        su += (u.y > 0.f ? mx.y : mn.y) * u.y;
        sl += (l.z > 0.f ? mn.z : mx.z) * l.z;
        su += (u.z > 0.f ? mx.z : mn.z) * u.z;
        sl += (l.w > 0.f ? mn.w : mx.w) * l.w;
        su += (u.w > 0.f ? mx.w : mn.w) * u.w;
    }

    // Warp reduction (no smem, no barrier).
    #pragma unroll
    for (int off = 16; off; off >>= 1) {
        sl += __shfl_down_sync(0xffffffffu, sl, off);
        su += __shfl_down_sync(0xffffffffu, su, off);
    }

    // Lane 0 finalizes scalars; broadcast decisions to the warp.
    float f_alive, f_cross, f_slope;
    if (lane == 0) {
        const float lcv = lc[n], ucv = uc[n];
        const float l = sl + lcv, u = su + ucv;
        const bool alive = (l >= 0.f);
        const bool cross = (l < 0.f) && (u > 0.f);
        float s = cross ? (u / (u - l)) : 1.f;
        s = fminf(fmaxf(s, 0.f), 1.f);
        lc_out[n] = alive ? lcv : 0.f;
        uc_out[n] = alive ? ucv : (cross ? (s * ucv - s * l) : 0.f);
        f_alive = alive ? 1.f : 0.f;
        f_cross = cross ? 1.f : 0.f;
        f_slope = s;
    }
    f_alive = __shfl_sync(0xffffffffu, f_alive, 0);
    f_cross = __shfl_sync(0xffffffffu, f_cross, 0);
    f_slope = __shfl_sync(0xffffffffu, f_slope, 0);

    const bool  alive = (f_alive != 0.f);
    const bool  cross = (f_cross != 0.f);
    const float slope = f_slope;

    float4* qlx = reinterpret_cast<float4*>(lx_out + base) + lane;
    float4* qux = reinterpret_cast<float4*>(ux_out + base) + lane;
    #pragma unroll
    for (int i = 0; i < 8; i++) {
        float4 o;
        o.x = alive ? vlx[i].x : 0.f;
        o.y = alive ? vlx[i].y : 0.f;
        o.z = alive ? vlx[i].z : 0.f;
        o.w = alive ? vlx[i].w : 0.f;
        __stcs(qlx + i * 32, o);
    }
    #pragma unroll
    for (int i = 0; i < 8; i++) {
        float4 o;
        o.x = alive ? vux[i].x : (cross ? slope * vux[i].x : 0.f);
        o.y = alive ? vux[i].y : (cross ? slope * vux[i].y : 0.f);
        o.z = alive ? vux[i].z : (cross ? slope * vux[i].z : 0.f);
        o.w = alive ? vux[i].w : (cross ? slope * vux[i].w : 0.f);
        __stcs(qux + i * 32, o);
    }
}

extern "C" void kernel_launch(void* const* d_in, const int* in_sizes, int n_in,
                              void* d_out, int out_size)
{
    const float* lx   = (const float*)d_in[0];
    const float* ux   = (const float*)d_in[1];
    const float* lc   = (const float*)d_in[2];
    const float* uc   = (const float*)d_in[3];
    const float* xmin = (const float*)d_in[4];
    const float* xmax = (const float*)d_in[5];

    const int neurons = in_sizes[2];          // C*H*W = 32768
    const size_t nel  = (size_t)neurons * 1024;

    float* out    = (float*)d_out;
    float* lx_out = out;
    float* ux_out = out + nel;
    float* lc_out = out + 2 * nel;
    float* uc_out = out + 2 * nel + neurons;

    relu_conv_warp_kernel<<<neurons / 8, 256>>>(lx, ux, lc, uc, xmin, xmax,
                                                lx_out, ux_out, lc_out, uc_out);
}

// round 6
// speedup vs baseline: 1.0818x; 1.0035x over previous
#include <cuda_runtime.h>

// ReLU_Conv (CROWN-style ReLU relaxation over bound maps)
// Round 6: 1 neuron per 128-thread block. Per-thread MLP=4 (2 float4 lx +
//          2 float4 ux, front-batched), streaming hints, single 4-warp
//          barrier, redundant per-thread finalize.
//          = R2's per-thread shape at ~75% theoretical occupancy.
// Output layout: [lx_out | ux_out | lc_out | uc_out]

__device__ __forceinline__ void acc_pair(const float4 l, const float4 u,
                                         const float4 mn, const float4 mx,
                                         float& sl, float& su)
{
    // (l>0 ? mn : (l<0 ? mx : 0)) * l == (l>0 ? mn : mx) * l  (finite bounds)
    sl += (l.x > 0.f ? mn.x : mx.x) * l.x;
    su += (u.x > 0.f ? mx.x : mn.x) * u.x;
    sl += (l.y > 0.f ? mn.y : mx.y) * l.y;
    su += (u.y > 0.f ? mx.y : mn.y) * u.y;
    sl += (l.z > 0.f ? mn.z : mx.z) * l.z;
    su += (u.z > 0.f ? mx.z : mn.z) * u.z;
    sl += (l.w > 0.f ? mn.w : mx.w) * l.w;
    su += (u.w > 0.f ? mx.w : mn.w) * u.w;
}

__global__ __launch_bounds__(128, 12)
void relu_conv_kernel(
    const float* __restrict__ lx, const float* __restrict__ ux,
    const float* __restrict__ lc, const float* __restrict__ uc,
    const float* __restrict__ xmin, const float* __restrict__ xmax,
    float* __restrict__ lx_out, float* __restrict__ ux_out,
    float* __restrict__ lc_out, float* __restrict__ uc_out)
{
    const int tid = threadIdx.x;                       // 0..127
    const int n   = blockIdx.x;                        // this block's neuron
    const size_t base = (size_t)n * 1024;

    // Front-batched streaming loads: 4x LDG.128 per thread.
    const float4* plx = reinterpret_cast<const float4*>(lx + base) + tid;
    const float4* pux = reinterpret_cast<const float4*>(ux + base) + tid;
    const float4 vlx0 = __ldcs(plx);
    const float4 vlx1 = __ldcs(plx + 128);
    const float4 vux0 = __ldcs(pux);
    const float4 vux1 = __ldcs(pux + 128);

    // Broadcast bounds: reused by all 32K blocks -> L1/L2 resident.
    const float4 vmn0 = __ldg(reinterpret_cast<const float4*>(xmin) + tid);
    const float4 vmn1 = __ldg(reinterpret_cast<const float4*>(xmin) + tid + 128);
    const float4 vmx0 = __ldg(reinterpret_cast<const float4*>(xmax) + tid);
    const float4 vmx1 = __ldg(reinterpret_cast<const float4*>(xmax) + tid + 128);

    float sl = 0.f, su = 0.f;
    acc_pair(vlx0, vux0, vmn0, vmx0, sl, su);
    acc_pair(vlx1, vux1, vmn1, vmx1, sl, su);

    // Warp reduction.
    #pragma unroll
    for (int off = 16; off; off >>= 1) {
        sl += __shfl_down_sync(0xffffffffu, sl, off);
        su += __shfl_down_sync(0xffffffffu, su, off);
    }

    __shared__ float2 sPart[4];                        // per-warp partials
    const int warp = tid >> 5, lane = tid & 31;
    if (lane == 0) sPart[warp] = make_float2(sl, su);
    __syncthreads();                                   // the ONLY barrier

    // Every thread redundantly finalizes (broadcast smem reads).
    const float2 p0 = sPart[0], p1 = sPart[1], p2 = sPart[2], p3 = sPart[3];
    const float lcv = lc[n], ucv = uc[n];
    const float l = (p0.x + p1.x) + (p2.x + p3.x) + lcv;
    const float u = (p0.y + p1.y) + (p2.y + p3.y) + ucv;

    const bool alive = (l >= 0.f);
    const bool cross = (l < 0.f) && (u > 0.f);
    float slope = cross ? (u / (u - l)) : 1.f;
    slope = fminf(fmaxf(slope, 0.f), 1.f);

    if (tid == 0) {
        lc_out[n] = alive ? lcv : 0.f;
        uc_out[n] = alive ? ucv : (cross ? (slope * ucv - slope * l) : 0.f);
    }

    float4* qlx = reinterpret_cast<float4*>(lx_out + base) + tid;
    float4* qux = reinterpret_cast<float4*>(ux_out + base) + tid;

    float4 o;
    o.x = alive ? vlx0.x : 0.f;  o.y = alive ? vlx0.y : 0.f;
    o.z = alive ? vlx0.z : 0.f;  o.w = alive ? vlx0.w : 0.f;
    __stcs(qlx, o);
    o.x = alive ? vlx1.x : 0.f;  o.y = alive ? vlx1.y : 0.f;
    o.z = alive ? vlx1.z : 0.f;  o.w = alive ? vlx1.w : 0.f;
    __stcs(qlx + 128, o);

    o.x = alive ? vux0.x : (cross ? slope * vux0.x : 0.f);
    o.y = alive ? vux0.y : (cross ? slope * vux0.y : 0.f);
    o.z = alive ? vux0.z : (cross ? slope * vux0.z : 0.f);
    o.w = alive ? vux0.w : (cross ? slope * vux0.w : 0.f);
    __stcs(qux, o);
    o.x = alive ? vux1.x : (cross ? slope * vux1.x : 0.f);
    o.y = alive ? vux1.y : (cross ? slope * vux1.y : 0.f);
    o.z = alive ? vux1.z : (cross ? slope * vux1.z : 0.f);
    o.w = alive ? vux1.w : (cross ? slope * vux1.w : 0.f);
    __stcs(qux + 128, o);
}

extern "C" void kernel_launch(void* const* d_in, const int* in_sizes, int n_in,
                              void* d_out, int out_size)
{
    const float* lx   = (const float*)d_in[0];
    const float* ux   = (const float*)d_in[1];
    const float* lc   = (const float*)d_in[2];
    const float* uc   = (const float*)d_in[3];
    const float* xmin = (const float*)d_in[4];
    const float* xmax = (const float*)d_in[5];

    const int neurons = in_sizes[2];          // C*H*W = 32768
    const size_t nel  = (size_t)neurons * 1024;

    float* out    = (float*)d_out;
    float* lx_out = out;
    float* ux_out = out + nel;
    float* lc_out = out + 2 * nel;
    float* uc_out = out + 2 * nel + neurons;

    relu_conv_kernel<<<neurons, 128>>>(lx, ux, lc, uc, xmin, xmax,
                                       lx_out, ux_out, lc_out, uc_out);
}